// round 2
// baseline (speedup 1.0000x reference)
#include <cuda_runtime.h>

// complexSelfMHA: B=4, H=16, S=1024, D=64, E=1024
// Inputs (metadata order): Re, Im, pos_enc, Wq, bq, Wk, bk, Wv, bv, Wo, bo
// Output: float32 [4, 1024, 1024]

#define BB 4
#define HH 16
#define SSQ 1024
#define DDIM 64
#define EE 1024
#define MM (BB * SSQ)  // 4096

// Scratch (device globals; no allocation allowed)
__device__ float g_Q[BB * HH * SSQ * DDIM];   // Q + P,  [b,h,s,d]
__device__ float g_K[BB * HH * SSQ * DDIM];   // K + P
__device__ float g_V[BB * HH * SSQ * DDIM];   // V + P
__device__ float g_Im[BB * HH * SSQ * DDIM];  // ImH     [b,h,s,d]
__device__ float g_AO[MM * EE];               // attention out, merged [b,s,e]

// ---------------------------------------------------------------------------
// Kernel 0: pack Im into [b,h,s,d]
// ---------------------------------------------------------------------------
__global__ void pack_im_kernel(const float* __restrict__ Im) {
    int idx = blockIdx.x * 256 + threadIdx.x;  // 0 .. 4*16*1024*64-1
    int d = idx & 63;
    int s = (idx >> 6) & 1023;
    int h = (idx >> 16) & 15;
    int b = idx >> 20;
    g_Im[idx] = Im[(b * SSQ + s) * EE + h * DDIM + d];
}

// ---------------------------------------------------------------------------
// Kernel 1: fused QKV projection GEMM.
// Y{q,k,v}[m,n] = sum_k Re[m,k] * W{q,k,v}[k,n] + b{q,k,v}[n]  (+ pos_enc)
// Block tile 64x64, BK=16, 256 threads, 4x4 per thread per weight.
// ---------------------------------------------------------------------------
__global__ __launch_bounds__(256) void qkv_gemm_kernel(
    const float* __restrict__ X,
    const float* __restrict__ Wq, const float* __restrict__ bq,
    const float* __restrict__ Wk, const float* __restrict__ bk,
    const float* __restrict__ Wv, const float* __restrict__ bv,
    const float* __restrict__ P)
{
    __shared__ float Xs[16][64];      // [k][m]
    __shared__ float Ws[3][16][64];   // [w][k][n]

    int m0 = blockIdx.y * 64;
    int n0 = blockIdx.x * 64;
    int t = threadIdx.x;
    int tx = t & 15, ty = t >> 4;

    float acc[3][4][4];
#pragma unroll
    for (int w = 0; w < 3; w++)
#pragma unroll
        for (int i = 0; i < 4; i++)
#pragma unroll
            for (int j = 0; j < 4; j++) acc[w][i][j] = 0.f;

    const float* Wp0 = Wq;
    const float* Wp1 = Wk;
    const float* Wp2 = Wv;

    int lm = t >> 2;            // 0..63 (row for X load)
    int lk = (t & 3) * 4;       // 0,4,8,12
    int wk = t >> 4;            // 0..15 (k for W load)
    int wn = (t & 15) * 4;      // 0..60

    for (int k0 = 0; k0 < EE; k0 += 16) {
        __syncthreads();
        // load X tile (transposed into Xs[k][m])
        {
            float4 v = *(const float4*)&X[(m0 + lm) * EE + k0 + lk];
            Xs[lk + 0][lm] = v.x;
            Xs[lk + 1][lm] = v.y;
            Xs[lk + 2][lm] = v.z;
            Xs[lk + 3][lm] = v.w;
        }
        // load W tiles
        {
            *(float4*)&Ws[0][wk][wn] = *(const float4*)&Wp0[(k0 + wk) * EE + n0 + wn];
            *(float4*)&Ws[1][wk][wn] = *(const float4*)&Wp1[(k0 + wk) * EE + n0 + wn];
            *(float4*)&Ws[2][wk][wn] = *(const float4*)&Wp2[(k0 + wk) * EE + n0 + wn];
        }
        __syncthreads();
#pragma unroll
        for (int kk = 0; kk < 16; kk++) {
            float4 a4 = *(const float4*)&Xs[kk][ty * 4];
            float av[4] = {a4.x, a4.y, a4.z, a4.w};
#pragma unroll
            for (int w = 0; w < 3; w++) {
                const float4 b4 = *(const float4*)&Ws[w][kk][tx * 4];
                float bv4[4] = {b4.x, b4.y, b4.z, b4.w};
#pragma unroll
                for (int i = 0; i < 4; i++)
#pragma unroll
                    for (int j = 0; j < 4; j++) acc[w][i][j] += av[i] * bv4[j];
            }
        }
    }

    // epilogue: add bias + pos_enc, scatter to [b,h,s,d]
#pragma unroll
    for (int i = 0; i < 4; i++) {
        int m = m0 + ty * 4 + i;
        int b = m >> 10, s = m & 1023;
#pragma unroll
        for (int j = 0; j < 4; j++) {
            int n = n0 + tx * 4 + j;
            int h = n >> 6, d = n & 63;
            float p = P[(b * SSQ + s) * DDIM + d];
            int o = (((b * HH + h) * SSQ + s) * DDIM + d);
            g_Q[o] = acc[0][i][j] + bq[n] + p;
            g_K[o] = acc[1][i][j] + bk[n] + p;
            g_V[o] = acc[2][i][j] + bv[n] + p;
        }
    }
}

// ---------------------------------------------------------------------------
// Kernel 2: flash attention with concatenated D'=128 ([Q|ImH] . [K|ImH]^T)
// grid: (S/64 q-tiles, B*H). Block 256 threads, 64 q-rows, K-tiles of 64.
// ---------------------------------------------------------------------------
#define QK_PAD 76     // row stride for Qst/Kst   (mult of 4 -> 16B aligned rows)
#define SV_PAD 68     // row stride for Sst/Vst
#define ATTN_SMEM_FLOATS (128 * QK_PAD * 2 + 64 * SV_PAD * 2 + 192)
#define ATTN_SMEM_BYTES (ATTN_SMEM_FLOATS * 4)

__global__ __launch_bounds__(256) void attn_kernel() {
    extern __shared__ float sm[];
    float* Qst = sm;                         // [128][QK_PAD] : Qst[k][r]
    float* Kst = Qst + 128 * QK_PAD;         // [128][QK_PAD] : Kst[k][c]
    float* Sst = Kst + 128 * QK_PAD;         // [64][SV_PAD]  : Sst[c][r]
    float* Vst = Sst + 64 * SV_PAD;          // [64][SV_PAD]  : Vst[c][d]
    float* row_m = Vst + 64 * SV_PAD;        // [64]
    float* row_l = row_m + 64;               // [64]
    float* alpha_s = row_l + 64;             // [64]

    int q0 = blockIdx.x * 64;
    int bh = blockIdx.y;
    int t = threadIdx.x, tx = t & 15, ty = t >> 4;
    const int base = bh * SSQ;

    // load Qst (transposed, concat Q | ImH)
    for (int e = t; e < 64 * 128; e += 256) {
        int r = e >> 7, k = e & 127;
        float v = (k < 64) ? g_Q[(base + q0 + r) * DDIM + k]
                           : g_Im[(base + q0 + r) * DDIM + (k - 64)];
        Qst[k * QK_PAD + r] = v;
    }
    if (t < 64) { row_m[t] = -1e30f; row_l[t] = 0.f; }

    float acc[4][4];
#pragma unroll
    for (int i = 0; i < 4; i++)
#pragma unroll
        for (int j = 0; j < 4; j++) acc[i][j] = 0.f;

    __syncthreads();

    const float inv_denom = 1.0f / 32.0f;  // 1/sqrt(1024)

    for (int kt = 0; kt < 16; kt++) {
        int k0 = kt * 64;
        // load K' tile (transposed, concat K | ImH) and V tile
        for (int e = t; e < 64 * 128; e += 256) {
            int r = e >> 7, k = e & 127;
            float v = (k < 64) ? g_K[(base + k0 + r) * DDIM + k]
                               : g_Im[(base + k0 + r) * DDIM + (k - 64)];
            Kst[k * QK_PAD + r] = v;
        }
        for (int e = t; e < 64 * 64; e += 256) {
            int c = e >> 6, d = e & 63;
            Vst[c * SV_PAD + d] = g_V[(base + k0 + c) * DDIM + d];
        }
        __syncthreads();

        // scores: S[r][c] = sum_k Q'[r][k] K'[c][k]
        float s[4][4];
#pragma unroll
        for (int i = 0; i < 4; i++)
#pragma unroll
            for (int j = 0; j < 4; j++) s[i][j] = 0.f;

#pragma unroll 8
        for (int k = 0; k < 128; k++) {
            float4 q4 = *(const float4*)&Qst[k * QK_PAD + ty * 4];
            float4 c4 = *(const float4*)&Kst[k * QK_PAD + tx * 4];
            s[0][0] += q4.x * c4.x; s[0][1] += q4.x * c4.y; s[0][2] += q4.x * c4.z; s[0][3] += q4.x * c4.w;
            s[1][0] += q4.y * c4.x; s[1][1] += q4.y * c4.y; s[1][2] += q4.y * c4.z; s[1][3] += q4.y * c4.w;
            s[2][0] += q4.z * c4.x; s[2][1] += q4.z * c4.y; s[2][2] += q4.z * c4.z; s[2][3] += q4.z * c4.w;
            s[3][0] += q4.w * c4.x; s[3][1] += q4.w * c4.y; s[3][2] += q4.w * c4.z; s[3][3] += q4.w * c4.w;
        }
#pragma unroll
        for (int i = 0; i < 4; i++)
#pragma unroll
            for (int j = 0; j < 4; j++)
                Sst[(tx * 4 + j) * SV_PAD + ty * 4 + i] = s[i][j] * inv_denom;
        __syncthreads();

        // online softmax over rows (64 worker threads, 1 row each)
        if (t < 64) {
            int r = t;
            float mx = -1e30f;
            for (int c = 0; c < 64; c++) mx = fmaxf(mx, Sst[c * SV_PAD + r]);
            float om = row_m[r];
            float nm = fmaxf(om, mx);
            float al = __expf(om - nm);
            float sum = 0.f;
            for (int c = 0; c < 64; c++) {
                float e2 = __expf(Sst[c * SV_PAD + r] - nm);
                Sst[c * SV_PAD + r] = e2;
                sum += e2;
            }
            row_l[r] = row_l[r] * al + sum;
            row_m[r] = nm;
            alpha_s[r] = al;
        }
        __syncthreads();

        // rescale accumulators + P @ V
        float al[4];
#pragma unroll
        for (int i = 0; i < 4; i++) al[i] = alpha_s[ty * 4 + i];
#pragma unroll
        for (int i = 0; i < 4; i++)
#pragma unroll
            for (int j = 0; j < 4; j++) acc[i][j] *= al[i];

#pragma unroll 8
        for (int c = 0; c < 64; c++) {
            float4 p4 = *(const float4*)&Sst[c * SV_PAD + ty * 4];
            float4 v4 = *(const float4*)&Vst[c * SV_PAD + tx * 4];
            acc[0][0] += p4.x * v4.x; acc[0][1] += p4.x * v4.y; acc[0][2] += p4.x * v4.z; acc[0][3] += p4.x * v4.w;
            acc[1][0] += p4.y * v4.x; acc[1][1] += p4.y * v4.y; acc[1][2] += p4.y * v4.z; acc[1][3] += p4.y * v4.w;
            acc[2][0] += p4.z * v4.x; acc[2][1] += p4.z * v4.y; acc[2][2] += p4.z * v4.z; acc[2][3] += p4.z * v4.w;
            acc[3][0] += p4.w * v4.x; acc[3][1] += p4.w * v4.y; acc[3][2] += p4.w * v4.z; acc[3][3] += p4.w * v4.w;
        }
        __syncthreads();  // before next tile overwrites Kst/Vst/Sst
    }

    // write merged output [b, s, h*64 + d]
    int b = bh >> 4, h = bh & 15;
#pragma unroll
    for (int i = 0; i < 4; i++) {
        int r = q0 + ty * 4 + i;
        float linv = 1.0f / row_l[ty * 4 + i];
#pragma unroll
        for (int j = 0; j < 4; j++) {
            g_AO[(b * SSQ + r) * EE + h * DDIM + tx * 4 + j] = acc[i][j] * linv;
        }
    }
}

// ---------------------------------------------------------------------------
// Kernel 3: output GEMM: out = g_AO @ Wo + bo
// ---------------------------------------------------------------------------
__global__ __launch_bounds__(256) void out_gemm_kernel(
    const float* __restrict__ W, const float* __restrict__ bias,
    float* __restrict__ out)
{
    __shared__ float Xs[16][64];
    __shared__ float Ws[16][64];

    int m0 = blockIdx.y * 64;
    int n0 = blockIdx.x * 64;
    int t = threadIdx.x;
    int tx = t & 15, ty = t >> 4;

    float acc[4][4];
#pragma unroll
    for (int i = 0; i < 4; i++)
#pragma unroll
        for (int j = 0; j < 4; j++) acc[i][j] = 0.f;

    int lm = t >> 2;
    int lk = (t & 3) * 4;
    int wk = t >> 4;
    int wn = (t & 15) * 4;

    for (int k0 = 0; k0 < EE; k0 += 16) {
        __syncthreads();
        {
            float4 v = *(const float4*)&g_AO[(m0 + lm) * EE + k0 + lk];
            Xs[lk + 0][lm] = v.x;
            Xs[lk + 1][lm] = v.y;
            Xs[lk + 2][lm] = v.z;
            Xs[lk + 3][lm] = v.w;
        }
        *(float4*)&Ws[wk][wn] = *(const float4*)&W[(k0 + wk) * EE + n0 + wn];
        __syncthreads();
#pragma unroll
        for (int kk = 0; kk < 16; kk++) {
            float4 a4 = *(const float4*)&Xs[kk][ty * 4];
            float4 b4 = *(const float4*)&Ws[kk][tx * 4];
            acc[0][0] += a4.x * b4.x; acc[0][1] += a4.x * b4.y; acc[0][2] += a4.x * b4.z; acc[0][3] += a4.x * b4.w;
            acc[1][0] += a4.y * b4.x; acc[1][1] += a4.y * b4.y; acc[1][2] += a4.y * b4.z; acc[1][3] += a4.y * b4.w;
            acc[2][0] += a4.z * b4.x; acc[2][1] += a4.z * b4.y; acc[2][2] += a4.z * b4.z; acc[2][3] += a4.z * b4.w;
            acc[3][0] += a4.w * b4.x; acc[3][1] += a4.w * b4.y; acc[3][2] += a4.w * b4.z; acc[3][3] += a4.w * b4.w;
        }
    }

#pragma unroll
    for (int i = 0; i < 4; i++) {
        int m = m0 + ty * 4 + i;
#pragma unroll
        for (int j = 0; j < 4; j++) {
            int n = n0 + tx * 4 + j;
            out[m * EE + n] = acc[i][j] + bias[n];
        }
    }
}

// ---------------------------------------------------------------------------
extern "C" void kernel_launch(void* const* d_in, const int* in_sizes, int n_in,
                              void* d_out, int out_size) {
    const float* Re  = (const float*)d_in[0];
    const float* Im  = (const float*)d_in[1];
    const float* pos = (const float*)d_in[2];
    const float* Wq  = (const float*)d_in[3];
    const float* bq  = (const float*)d_in[4];
    const float* Wk  = (const float*)d_in[5];
    const float* bk  = (const float*)d_in[6];
    const float* Wv  = (const float*)d_in[7];
    const float* bv  = (const float*)d_in[8];
    const float* Wo  = (const float*)d_in[9];
    const float* bo  = (const float*)d_in[10];
    float* out = (float*)d_out;

    cudaFuncSetAttribute(attn_kernel, cudaFuncAttributeMaxDynamicSharedMemorySize,
                         ATTN_SMEM_BYTES);

    pack_im_kernel<<<(BB * HH * SSQ * DDIM) / 256, 256>>>(Im);
    qkv_gemm_kernel<<<dim3(EE / 64, MM / 64), 256>>>(Re, Wq, bq, Wk, bk, Wv, bv, pos);
    attn_kernel<<<dim3(SSQ / 64, BB * HH), 256, ATTN_SMEM_BYTES>>>();
    out_gemm_kernel<<<dim3(EE / 64, MM / 64), 256>>>(Wo, bo, out);
}

// round 8
// speedup vs baseline: 2.3449x; 2.3449x over previous
#include <cuda_runtime.h>

// complexSelfMHA: B=4, H=16, S=1024, D=64, E=1024
// Inputs: Re, Im, pos_enc, Wq, bq, Wk, bk, Wv, bv, Wo, bo ; out fp32 [4,1024,1024]

#define BB 4
#define HH 16
#define SSQ 1024
#define DDIM 64
#define EE 1024
#define MM (BB * SSQ)   // 4096
#define NBH (BB * HH)   // 64

// Scratch (device globals)
__device__ float g_Q[NBH * SSQ * DDIM];    // [bh][s][d]  (Q + P)
__device__ float g_Kt[NBH * DDIM * SSQ];   // [bh][d][s]  (K + P, transposed)
__device__ float g_V[NBH * SSQ * DDIM];    // [bh][s][d]  (V + P)
__device__ float g_Im[NBH * SSQ * DDIM];   // [bh][s][d]
__device__ float g_Imt[NBH * DDIM * SSQ];  // [bh][d][s]
__device__ float g_AO[MM * EE];            // merged attn out [b,s,e]

__device__ __forceinline__ unsigned f2tf(float x) {
    unsigned u;
    asm("cvt.rna.tf32.f32 %0, %1;" : "=r"(u) : "f"(x));
    return u;
}

__device__ __forceinline__ void mma8(float* c, const unsigned* a, const unsigned* b) {
    asm volatile(
        "mma.sync.aligned.m16n8k8.row.col.f32.tf32.tf32.f32 "
        "{%0,%1,%2,%3},{%4,%5,%6,%7},{%8,%9},{%0,%1,%2,%3};"
        : "+f"(c[0]), "+f"(c[1]), "+f"(c[2]), "+f"(c[3])
        : "r"(a[0]), "r"(a[1]), "r"(a[2]), "r"(a[3]), "r"(b[0]), "r"(b[1]));
}

// ---------------------------------------------------------------------------
// Kernel 0: pack Im into [bh][s][d] and [bh][d][s]
// ---------------------------------------------------------------------------
__global__ void pack_im_kernel(const float* __restrict__ Im) {
    int idx = blockIdx.x * 256 + threadIdx.x;  // over NBH*SSQ*DDIM
    int d = idx & 63;
    int s = (idx >> 6) & 1023;
    int h = (idx >> 16) & 15;
    int b = idx >> 20;
    float v = Im[(b * SSQ + s) * EE + h * DDIM + d];
    g_Im[idx] = v;
    g_Imt[(((b * HH + h) * DDIM) + d) * SSQ + s] = v;
}

// ---------------------------------------------------------------------------
// Kernel 1: fused QKV projection, tensor cores (tf32).
// grid (8 n128, 32 m128, 3 w); block 256 (8 warps, 2x4), warp tile 64x32.
// ---------------------------------------------------------------------------
#define AST 36
#define BST 132

__global__ __launch_bounds__(256) void qkv_tc_kernel(
    const float* __restrict__ X,
    const float* __restrict__ Wq, const float* __restrict__ Wk, const float* __restrict__ Wv,
    const float* __restrict__ bq, const float* __restrict__ bk, const float* __restrict__ bv,
    const float* __restrict__ P)
{
    __shared__ unsigned As[128 * AST];  // [m][k] tf32
    __shared__ unsigned Bs[32 * BST];   // [k][n] tf32

    int w = blockIdx.z;
    const float* W    = (w == 0) ? Wq : (w == 1) ? Wk : Wv;
    const float* bias = (w == 0) ? bq : (w == 1) ? bk : bv;

    int m0 = blockIdx.y * 128, n0 = blockIdx.x * 128;
    int t = threadIdx.x, lane = t & 31, wid = t >> 5;
    int wm = (wid & 1) * 64, wn = (wid >> 1) * 32;

    float C[4][4][4];
#pragma unroll
    for (int mt = 0; mt < 4; mt++)
#pragma unroll
        for (int nt = 0; nt < 4; nt++)
#pragma unroll
            for (int i = 0; i < 4; i++) C[mt][nt][i] = 0.f;

    int arow = t >> 3, acol = (t & 7) * 4;   // +p*32 rows
    int brow = t >> 5, bcol = (t & 31) * 4;  // +p*8 k-rows

    float4 pa[4], pb[4];
#pragma unroll
    for (int p = 0; p < 4; p++) {
        pa[p] = *(const float4*)&X[(m0 + arow + p * 32) * EE + acol];
        pb[p] = *(const float4*)&W[(brow + p * 8) * EE + n0 + bcol];
    }

    for (int k0 = 0; k0 < EE; k0 += 32) {
#pragma unroll
        for (int p = 0; p < 4; p++) {
            unsigned* a = &As[(arow + p * 32) * AST + acol];
            a[0] = f2tf(pa[p].x); a[1] = f2tf(pa[p].y); a[2] = f2tf(pa[p].z); a[3] = f2tf(pa[p].w);
            unsigned* bp = &Bs[(brow + p * 8) * BST + bcol];
            bp[0] = f2tf(pb[p].x); bp[1] = f2tf(pb[p].y); bp[2] = f2tf(pb[p].z); bp[3] = f2tf(pb[p].w);
        }
        __syncthreads();
        if (k0 + 32 < EE) {
#pragma unroll
            for (int p = 0; p < 4; p++) {
                pa[p] = *(const float4*)&X[(m0 + arow + p * 32) * EE + k0 + 32 + acol];
                pb[p] = *(const float4*)&W[(k0 + 32 + brow + p * 8) * EE + n0 + bcol];
            }
        }
#pragma unroll
        for (int ks = 0; ks < 4; ks++) {
            unsigned af[4][4], bf[4][2];
#pragma unroll
            for (int mt = 0; mt < 4; mt++) {
                int r = wm + mt * 16 + (lane >> 2);
                int ck = ks * 8 + (lane & 3);
                af[mt][0] = As[r * AST + ck];
                af[mt][1] = As[(r + 8) * AST + ck];
                af[mt][2] = As[r * AST + ck + 4];
                af[mt][3] = As[(r + 8) * AST + ck + 4];
            }
#pragma unroll
            for (int nt = 0; nt < 4; nt++) {
                int kk = ks * 8 + (lane & 3);
                int cn = wn + nt * 8 + (lane >> 2);
                bf[nt][0] = Bs[kk * BST + cn];
                bf[nt][1] = Bs[(kk + 4) * BST + cn];
            }
#pragma unroll
            for (int mt = 0; mt < 4; mt++)
#pragma unroll
                for (int nt = 0; nt < 4; nt++) mma8(C[mt][nt], af[mt], bf[nt]);
        }
        __syncthreads();
    }

    // epilogue: + bias + pos_enc; Q/V -> [bh][s][d]; K -> [bh][d][s]
#pragma unroll
    for (int mt = 0; mt < 4; mt++) {
#pragma unroll
        for (int rr = 0; rr < 2; rr++) {
            int m = m0 + wm + mt * 16 + (lane >> 2) + rr * 8;
            int b = m >> 10, s = m & 1023;
#pragma unroll
            for (int nt = 0; nt < 4; nt++) {
                int c = n0 + wn + nt * 8 + (lane & 3) * 2;
                int h = c >> 6, d = c & 63;
                const float* pp = &P[(b * SSQ + s) * DDIM + d];
                float v0 = C[mt][nt][rr * 2 + 0] + bias[c] + pp[0];
                float v1 = C[mt][nt][rr * 2 + 1] + bias[c + 1] + pp[1];
                int bh = b * HH + h;
                if (w == 1) {
                    g_Kt[(bh * DDIM + d) * SSQ + s] = v0;
                    g_Kt[(bh * DDIM + d + 1) * SSQ + s] = v1;
                } else {
                    float* dst = (w == 0) ? g_Q : g_V;
                    *(float2*)&dst[(bh * SSQ + s) * DDIM + d] = make_float2(v0, v1);
                }
            }
        }
    }
}

// ---------------------------------------------------------------------------
// Kernel 2: flash attention, tensor cores. q-tile 128, k-tile 64, D'=128.
// grid (8 q-tiles, 64 bh); 256 threads = 8 warps, warp = 16 q-rows.
// ---------------------------------------------------------------------------
#define QST 132
#define KST 68
#define VST 68
#define SST 68
#define ATTN_WORDS (128 * QST + 128 * KST + 64 * VST + 128 * SST + 3 * 128)
#define ATTN_SMEM_BYTES (ATTN_WORDS * 4)

__global__ __launch_bounds__(256) void attn_tc_kernel() {
    extern __shared__ unsigned su[];
    unsigned* Qst = su;                        // [r][k] 128x132
    unsigned* Kst = Qst + 128 * QST;           // [k(feature)][c] 128x68
    unsigned* Vst = Kst + 128 * KST;           // [c][d] 64x68
    float*    Sst = (float*)(Vst + 64 * VST);  // [r][c] 128x68
    float*    row_m = Sst + 128 * SST;
    float*    row_l = row_m + 128;
    float*    alpha = row_l + 128;

    int q0 = blockIdx.x * 128;
    int bh = blockIdx.y;
    int t = threadIdx.x, lane = t & 31, wid = t >> 5;
    int m0w = wid * 16;
    const int base = bh * SSQ;
    const float scale = 0.03125f;  // 1/sqrt(1024)

    // load Q' = [Q | Im] rows q0..q0+127, tf32
#pragma unroll
    for (int p = 0; p < 16; p++) {
        int idx = t + 256 * p;           // 4096 float4s
        int r = idx >> 5, c4 = idx & 31; // k = c4*4
        int k = c4 * 4;
        const float* src = (k < 64) ? &g_Q[(base + q0 + r) * DDIM + k]
                                    : &g_Im[(base + q0 + r) * DDIM + k - 64];
        float4 v = *(const float4*)src;
        unsigned* dst = &Qst[r * QST + k];
        dst[0] = f2tf(v.x); dst[1] = f2tf(v.y); dst[2] = f2tf(v.z); dst[3] = f2tf(v.w);
    }
    if (t < 128) { row_m[t] = -1e30f; row_l[t] = 0.f; }

    float OC[8][4];
#pragma unroll
    for (int nt = 0; nt < 8; nt++)
#pragma unroll
        for (int i = 0; i < 4; i++) OC[nt][i] = 0.f;

    __syncthreads();

    for (int kt = 0; kt < 16; kt++) {
        int k0 = kt * 64;
        // load K' tile [feature 0..127][c 0..63] from g_Kt/g_Imt (coalesced rows)
#pragma unroll
        for (int p = 0; p < 8; p++) {
            int idx = t + 256 * p;            // 2048 float4s
            int kk = idx >> 4, c4 = idx & 15; // c = c4*4
            int c = c4 * 4;
            const float* src = (kk < 64) ? &g_Kt[(bh * DDIM + kk) * SSQ + k0 + c]
                                         : &g_Imt[(bh * DDIM + kk - 64) * SSQ + k0 + c];
            float4 v = *(const float4*)src;
            unsigned* dst = &Kst[kk * KST + c];
            dst[0] = f2tf(v.x); dst[1] = f2tf(v.y); dst[2] = f2tf(v.z); dst[3] = f2tf(v.w);
        }
        // load V tile [c 0..63][d 0..63]
#pragma unroll
        for (int p = 0; p < 4; p++) {
            int idx = t + 256 * p;           // 1024 float4s
            int c = idx >> 4, d4 = idx & 15;
            int d = d4 * 4;
            float4 v = *(const float4*)&g_V[(base + k0 + c) * DDIM + d];
            unsigned* dst = &Vst[c * VST + d];
            dst[0] = f2tf(v.x); dst[1] = f2tf(v.y); dst[2] = f2tf(v.z); dst[3] = f2tf(v.w);
        }
        __syncthreads();

        // S = Q' K'^T  (M=128 rows /8 warps, N=64, K=128)
        float SC[8][4];
#pragma unroll
        for (int nt = 0; nt < 8; nt++)
#pragma unroll
            for (int i = 0; i < 4; i++) SC[nt][i] = 0.f;

#pragma unroll
        for (int ks = 0; ks < 16; ks++) {
            unsigned af[4];
            int r = m0w + (lane >> 2);
            int ck = ks * 8 + (lane & 3);
            af[0] = Qst[r * QST + ck];
            af[1] = Qst[(r + 8) * QST + ck];
            af[2] = Qst[r * QST + ck + 4];
            af[3] = Qst[(r + 8) * QST + ck + 4];
#pragma unroll
            for (int nt = 0; nt < 8; nt++) {
                unsigned bf[2];
                int kk = ks * 8 + (lane & 3);
                int cn = nt * 8 + (lane >> 2);
                bf[0] = Kst[kk * KST + cn];
                bf[1] = Kst[(kk + 4) * KST + cn];
                mma8(SC[nt], af, bf);
            }
        }
        // store scaled scores (fp32) to Sst
#pragma unroll
        for (int nt = 0; nt < 8; nt++) {
            int cc = nt * 8 + (lane & 3) * 2;
            int r = m0w + (lane >> 2);
            *(float2*)&Sst[r * SST + cc] = make_float2(SC[nt][0] * scale, SC[nt][1] * scale);
            *(float2*)&Sst[(r + 8) * SST + cc] = make_float2(SC[nt][2] * scale, SC[nt][3] * scale);
        }
        __syncthreads();

        // online softmax: 2 threads per row
        {
            int r = t >> 1, c0 = (t & 1) * 32;
            float mx = -1e30f;
#pragma unroll
            for (int i = 0; i < 32; i++) mx = fmaxf(mx, Sst[r * SST + c0 + i]);
            mx = fmaxf(mx, __shfl_xor_sync(0xffffffffu, mx, 1));
            float om = row_m[r];
            float nm = fmaxf(om, mx);
            float al = __expf(om - nm);
            float sum = 0.f;
#pragma unroll
            for (int i = 0; i < 32; i++) {
                float e = __expf(Sst[r * SST + c0 + i] - nm);
                sum += e;
                Sst[r * SST + c0 + i] = __uint_as_float(f2tf(e));
            }
            sum += __shfl_xor_sync(0xffffffffu, sum, 1);
            if ((t & 1) == 0) {
                row_l[r] = row_l[r] * al + sum;
                row_m[r] = nm;
                alpha[r] = al;
            }
        }
        __syncthreads();

        // rescale O accumulators
        {
            float al0 = alpha[m0w + (lane >> 2)];
            float al1 = alpha[m0w + (lane >> 2) + 8];
#pragma unroll
            for (int nt = 0; nt < 8; nt++) {
                OC[nt][0] *= al0; OC[nt][1] *= al0;
                OC[nt][2] *= al1; OC[nt][3] *= al1;
            }
        }

        // O += P @ V  (K=64)
        const unsigned* Su = (const unsigned*)Sst;
#pragma unroll
        for (int ks = 0; ks < 8; ks++) {
            unsigned af[4];
            int r = m0w + (lane >> 2);
            int ck = ks * 8 + (lane & 3);
            af[0] = Su[r * SST + ck];
            af[1] = Su[(r + 8) * SST + ck];
            af[2] = Su[r * SST + ck + 4];
            af[3] = Su[(r + 8) * SST + ck + 4];
#pragma unroll
            for (int nt = 0; nt < 8; nt++) {
                unsigned bf[2];
                int kk = ks * 8 + (lane & 3);
                int dn = nt * 8 + (lane >> 2);
                bf[0] = Vst[kk * VST + dn];
                bf[1] = Vst[(kk + 4) * VST + dn];
                mma8(OC[nt], af, bf);
            }
        }
        __syncthreads();
    }

    // finalize: /row_l, write merged [b, s, h*64+d]
    int b = bh >> 4, h = bh & 15;
    {
        int r0 = m0w + (lane >> 2);
        float li0 = 1.0f / row_l[r0];
        float li1 = 1.0f / row_l[r0 + 8];
#pragma unroll
        for (int nt = 0; nt < 8; nt++) {
            int d = nt * 8 + (lane & 3) * 2;
            int s0 = q0 + r0;
            *(float2*)&g_AO[(b * SSQ + s0) * EE + h * DDIM + d] =
                make_float2(OC[nt][0] * li0, OC[nt][1] * li0);
            *(float2*)&g_AO[(b * SSQ + s0 + 8) * EE + h * DDIM + d] =
                make_float2(OC[nt][2] * li1, OC[nt][3] * li1);
        }
    }
}

// ---------------------------------------------------------------------------
// Kernel 3: output GEMM (tensor cores): out = g_AO @ Wo + bo
// ---------------------------------------------------------------------------
__global__ __launch_bounds__(256) void out_tc_kernel(
    const float* __restrict__ W, const float* __restrict__ bias,
    float* __restrict__ out)
{
    __shared__ unsigned As[128 * AST];
    __shared__ unsigned Bs[32 * BST];

    int m0 = blockIdx.y * 128, n0 = blockIdx.x * 128;
    int t = threadIdx.x, lane = t & 31, wid = t >> 5;
    int wm = (wid & 1) * 64, wn = (wid >> 1) * 32;

    float C[4][4][4];
#pragma unroll
    for (int mt = 0; mt < 4; mt++)
#pragma unroll
        for (int nt = 0; nt < 4; nt++)
#pragma unroll
            for (int i = 0; i < 4; i++) C[mt][nt][i] = 0.f;

    int arow = t >> 3, acol = (t & 7) * 4;
    int brow = t >> 5, bcol = (t & 31) * 4;

    float4 pa[4], pb[4];
#pragma unroll
    for (int p = 0; p < 4; p++) {
        pa[p] = *(const float4*)&g_AO[(m0 + arow + p * 32) * EE + acol];
        pb[p] = *(const float4*)&W[(brow + p * 8) * EE + n0 + bcol];
    }

    for (int k0 = 0; k0 < EE; k0 += 32) {
#pragma unroll
        for (int p = 0; p < 4; p++) {
            unsigned* a = &As[(arow + p * 32) * AST + acol];
            a[0] = f2tf(pa[p].x); a[1] = f2tf(pa[p].y); a[2] = f2tf(pa[p].z); a[3] = f2tf(pa[p].w);
            unsigned* bp = &Bs[(brow + p * 8) * BST + bcol];
            bp[0] = f2tf(pb[p].x); bp[1] = f2tf(pb[p].y); bp[2] = f2tf(pb[p].z); bp[3] = f2tf(pb[p].w);
        }
        __syncthreads();
        if (k0 + 32 < EE) {
#pragma unroll
            for (int p = 0; p < 4; p++) {
                pa[p] = *(const float4*)&g_AO[(m0 + arow + p * 32) * EE + k0 + 32 + acol];
                pb[p] = *(const float4*)&W[(k0 + 32 + brow + p * 8) * EE + n0 + bcol];
            }
        }
#pragma unroll
        for (int ks = 0; ks < 4; ks++) {
            unsigned af[4][4], bf[4][2];
#pragma unroll
            for (int mt = 0; mt < 4; mt++) {
                int r = wm + mt * 16 + (lane >> 2);
                int ck = ks * 8 + (lane & 3);
                af[mt][0] = As[r * AST + ck];
                af[mt][1] = As[(r + 8) * AST + ck];
                af[mt][2] = As[r * AST + ck + 4];
                af[mt][3] = As[(r + 8) * AST + ck + 4];
            }
#pragma unroll
            for (int nt = 0; nt < 4; nt++) {
                int kk = ks * 8 + (lane & 3);
                int cn = wn + nt * 8 + (lane >> 2);
                bf[nt][0] = Bs[kk * BST + cn];
                bf[nt][1] = Bs[(kk + 4) * BST + cn];
            }
#pragma unroll
            for (int mt = 0; mt < 4; mt++)
#pragma unroll
                for (int nt = 0; nt < 4; nt++) mma8(C[mt][nt], af[mt], bf[nt]);
        }
        __syncthreads();
    }

#pragma unroll
    for (int mt = 0; mt < 4; mt++) {
#pragma unroll
        for (int rr = 0; rr < 2; rr++) {
            int m = m0 + wm + mt * 16 + (lane >> 2) + rr * 8;
#pragma unroll
            for (int nt = 0; nt < 4; nt++) {
                int c = n0 + wn + nt * 8 + (lane & 3) * 2;
                float v0 = C[mt][nt][rr * 2 + 0] + bias[c];
                float v1 = C[mt][nt][rr * 2 + 1] + bias[c + 1];
                *(float2*)&out[m * EE + c] = make_float2(v0, v1);
            }
        }
    }
}

// ---------------------------------------------------------------------------
extern "C" void kernel_launch(void* const* d_in, const int* in_sizes, int n_in,
                              void* d_out, int out_size) {
    const float* Re  = (const float*)d_in[0];
    const float* Im  = (const float*)d_in[1];
    const float* pos = (const float*)d_in[2];
    const float* Wq  = (const float*)d_in[3];
    const float* bq  = (const float*)d_in[4];
    const float* Wk  = (const float*)d_in[5];
    const float* bk  = (const float*)d_in[6];
    const float* Wv  = (const float*)d_in[7];
    const float* bv  = (const float*)d_in[8];
    const float* Wo  = (const float*)d_in[9];
    const float* bo  = (const float*)d_in[10];
    float* out = (float*)d_out;

    cudaFuncSetAttribute(attn_tc_kernel, cudaFuncAttributeMaxDynamicSharedMemorySize,
                         ATTN_SMEM_BYTES);

    pack_im_kernel<<<(NBH * SSQ * DDIM) / 256, 256>>>(Im);
    qkv_tc_kernel<<<dim3(EE / 128, MM / 128, 3), 256>>>(Re, Wq, Wk, Wv, bq, bk, bv, pos);
    attn_tc_kernel<<<dim3(SSQ / 128, NBH), 256, ATTN_SMEM_BYTES>>>();
    out_tc_kernel<<<dim3(EE / 128, MM / 128), 256>>>(Wo, bo, out);
}

// round 14
// speedup vs baseline: 2.4383x; 1.0398x over previous
#include <cuda_runtime.h>

// complexSelfMHA: B=4, H=16, S=1024, D=64, E=1024
// Inputs: Re, Im, pos_enc, Wq, bq, Wk, bk, Wv, bv, Wo, bo ; out fp32 [4,1024,1024]

#define BB 4
#define HH 16
#define SSQ 1024
#define DDIM 64
#define EE 1024
#define MM (BB * SSQ)   // 4096
#define NBH (BB * HH)   // 64

// Scratch (device globals). All tf32-pre-rounded (low 13 mantissa bits zero).
__device__ float g_Ret[MM * EE];           // Re, tf32-rounded
__device__ float g_Wc[4][EE * EE];         // Wq,Wk,Wv,Wo tf32-rounded
__device__ float g_Q[NBH * SSQ * DDIM];    // [bh][s][d]  (Q + P)
__device__ float g_Kt[NBH * DDIM * SSQ];   // [bh][d][s]  (K + P, transposed)
__device__ float g_V[NBH * SSQ * DDIM];    // [bh][s][d]  (V + P)
__device__ float g_Im[NBH * SSQ * DDIM];   // [bh][s][d]
__device__ float g_Imt[NBH * DDIM * SSQ];  // [bh][d][s]
__device__ float g_AO[MM * EE];            // merged attn out [b,s,e]

__device__ __forceinline__ unsigned f2tf(float x) {
    unsigned u;
    asm("cvt.rna.tf32.f32 %0, %1;" : "=r"(u) : "f"(x));
    return u;
}
__device__ __forceinline__ float rtf(float x) { return __uint_as_float(f2tf(x)); }

__device__ __forceinline__ void mma8(float* c, const unsigned* a, const unsigned* b) {
    asm volatile(
        "mma.sync.aligned.m16n8k8.row.col.f32.tf32.tf32.f32 "
        "{%0,%1,%2,%3},{%4,%5,%6,%7},{%8,%9},{%0,%1,%2,%3};"
        : "+f"(c[0]), "+f"(c[1]), "+f"(c[2]), "+f"(c[3])
        : "r"(a[0]), "r"(a[1]), "r"(a[2]), "r"(a[3]), "r"(b[0]), "r"(b[1]));
}

__device__ __forceinline__ void cpa16(void* dst, const void* src) {
    unsigned s = (unsigned)__cvta_generic_to_shared(dst);
    asm volatile("cp.async.ca.shared.global [%0], [%1], 16;" :: "r"(s), "l"(src));
}
#define CP_COMMIT() asm volatile("cp.async.commit_group;")
#define CP_WAIT(n)  asm volatile("cp.async.wait_group %0;" :: "n"(n))

// ---------------------------------------------------------------------------
// Kernel A: tf32 convert (which: 0 -> g_Ret, 1..4 -> g_Wc[0..3])
// ---------------------------------------------------------------------------
__global__ void conv_tf32_kernel(const float* __restrict__ src, int which) {
    int i = blockIdx.x * 256 + threadIdx.x;
    float* dst = (which == 0) ? g_Ret : g_Wc[which - 1];
    dst[i] = rtf(src[i]);
}

// ---------------------------------------------------------------------------
// Kernel 0: pack Im (tf32-rounded) into [bh][s][d] and [bh][d][s]
// ---------------------------------------------------------------------------
__global__ void pack_im_kernel(const float* __restrict__ Im) {
    int idx = blockIdx.x * 256 + threadIdx.x;
    int d = idx & 63;
    int s = (idx >> 6) & 1023;
    int h = (idx >> 16) & 15;
    int b = idx >> 20;
    float v = rtf(Im[(b * SSQ + s) * EE + h * DDIM + d]);
    g_Im[idx] = v;
    g_Imt[(((b * HH + h) * DDIM) + d) * SSQ + s] = v;
}

// ---------------------------------------------------------------------------
// Kernel 1: fused QKV projection, tf32 tensor cores + cp.async double buffer.
// grid (8 n128, 32 m128, 3 w); block 256 (8 warps), warp tile 64x32, BK=32.
// ---------------------------------------------------------------------------
#define AST 36
#define BST 132
#define ASZ (128 * AST)
#define BSZ (32 * BST)
#define GEMM_SMEM_BYTES ((2 * ASZ + 2 * BSZ) * 4)

__device__ __forceinline__ void gemm_load_tiles(
    unsigned* As, unsigned* Bs, int buf,
    const float* X, const float* W, int m0, int n0, int k0, int t)
{
#pragma unroll
    for (int p = 0; p < 4; p++) {
        int c = t + p * 256;
        int ar = c >> 3, ac = (c & 7) * 4;
        cpa16(&As[buf * ASZ + ar * AST + ac], &X[(m0 + ar) * EE + k0 + ac]);
        int br = c >> 5, bc = (c & 31) * 4;
        cpa16(&Bs[buf * BSZ + br * BST + bc], &W[(k0 + br) * EE + n0 + bc]);
    }
}

__device__ __forceinline__ void gemm_compute(
    const unsigned* As, const unsigned* Bs, int buf,
    float C[4][4][4], int wm, int wn, int lane)
{
    const unsigned* A = As + buf * ASZ;
    const unsigned* B = Bs + buf * BSZ;
#pragma unroll
    for (int ks = 0; ks < 4; ks++) {
        unsigned af[4][4], bf[4][2];
#pragma unroll
        for (int mt = 0; mt < 4; mt++) {
            int r = wm + mt * 16 + (lane >> 2);
            int ck = ks * 8 + (lane & 3);
            af[mt][0] = A[r * AST + ck];
            af[mt][1] = A[(r + 8) * AST + ck];
            af[mt][2] = A[r * AST + ck + 4];
            af[mt][3] = A[(r + 8) * AST + ck + 4];
        }
#pragma unroll
        for (int nt = 0; nt < 4; nt++) {
            int kk = ks * 8 + (lane & 3);
            int cn = wn + nt * 8 + (lane >> 2);
            bf[nt][0] = B[kk * BST + cn];
            bf[nt][1] = B[(kk + 4) * BST + cn];
        }
#pragma unroll
        for (int mt = 0; mt < 4; mt++)
#pragma unroll
            for (int nt = 0; nt < 4; nt++) mma8(C[mt][nt], af[mt], bf[nt]);
    }
}

__global__ __launch_bounds__(256) void qkv_tc_kernel(
    const float* __restrict__ bq, const float* __restrict__ bk,
    const float* __restrict__ bv, const float* __restrict__ P)
{
    extern __shared__ unsigned gsm[];
    unsigned* As = gsm;
    unsigned* Bs = gsm + 2 * ASZ;

    int w = blockIdx.z;
    const float* W    = g_Wc[w];
    const float* bias = (w == 0) ? bq : (w == 1) ? bk : bv;

    int m0 = blockIdx.y * 128, n0 = blockIdx.x * 128;
    int t = threadIdx.x, lane = t & 31, wid = t >> 5;
    int wm = (wid & 1) * 64, wn = (wid >> 1) * 32;

    float C[4][4][4];
#pragma unroll
    for (int mt = 0; mt < 4; mt++)
#pragma unroll
        for (int nt = 0; nt < 4; nt++)
#pragma unroll
            for (int i = 0; i < 4; i++) C[mt][nt][i] = 0.f;

    const int NSTEP = EE / 32;
    gemm_load_tiles(As, Bs, 0, g_Ret, W, m0, n0, 0, t);
    CP_COMMIT();

    for (int it = 0; it < NSTEP; it++) {
        int buf = it & 1;
        if (it + 1 < NSTEP) {
            gemm_load_tiles(As, Bs, buf ^ 1, g_Ret, W, m0, n0, (it + 1) * 32, t);
            CP_COMMIT();
            CP_WAIT(1);
        } else {
            CP_WAIT(0);
        }
        __syncthreads();
        gemm_compute(As, Bs, buf, C, wm, wn, lane);
        __syncthreads();
    }

    // epilogue: + bias + pos_enc, tf32-round; Q/V -> [bh][s][d]; K -> [bh][d][s]
#pragma unroll
    for (int mt = 0; mt < 4; mt++) {
#pragma unroll
        for (int rr = 0; rr < 2; rr++) {
            int m = m0 + wm + mt * 16 + (lane >> 2) + rr * 8;
            int b = m >> 10, s = m & 1023;
#pragma unroll
            for (int nt = 0; nt < 4; nt++) {
                int c = n0 + wn + nt * 8 + (lane & 3) * 2;
                int h = c >> 6, d = c & 63;
                const float* pp = &P[(b * SSQ + s) * DDIM + d];
                float v0 = rtf(C[mt][nt][rr * 2 + 0] + bias[c] + pp[0]);
                float v1 = rtf(C[mt][nt][rr * 2 + 1] + bias[c + 1] + pp[1]);
                int bh = b * HH + h;
                if (w == 1) {
                    g_Kt[(bh * DDIM + d) * SSQ + s] = v0;
                    g_Kt[(bh * DDIM + d + 1) * SSQ + s] = v1;
                } else {
                    float* dst = (w == 0) ? g_Q : g_V;
                    *(float2*)&dst[(bh * SSQ + s) * DDIM + d] = make_float2(v0, v1);
                }
            }
        }
    }
}

// ---------------------------------------------------------------------------
// Kernel 2: flash attention, tf32 TC, cp.async double-buffered K/V tiles.
// q-tile 128, k-tile 64, D'=128. grid (8, 64 bh); 256 thr = 8 warps.
// ---------------------------------------------------------------------------
#define QST 132
#define KST 68
#define VST 68
#define SST 68
#define KSZ (128 * KST)
#define VSZ (64 * VST)
#define ATTN_WORDS (128 * QST + 2 * KSZ + 2 * VSZ + 128 * SST + 3 * 128)
#define ATTN_SMEM_BYTES (ATTN_WORDS * 4)

__device__ __forceinline__ void attn_load_kv(
    unsigned* Kst, unsigned* Vst, int buf, int bh, int base, int k0, int t)
{
#pragma unroll
    for (int p = 0; p < 8; p++) {
        int c = t + p * 256;              // 2048 chunks: K' tile
        int kk = c >> 4, cc = (c & 15) * 4;
        const float* src = (kk < 64) ? &g_Kt[(bh * DDIM + kk) * SSQ + k0 + cc]
                                     : &g_Imt[(bh * DDIM + kk - 64) * SSQ + k0 + cc];
        cpa16(&Kst[buf * KSZ + kk * KST + cc], src);
    }
#pragma unroll
    for (int p = 0; p < 4; p++) {
        int c = t + p * 256;              // 1024 chunks: V tile
        int r = c >> 4, cc = (c & 15) * 4;
        cpa16(&Vst[buf * VSZ + r * VST + cc], &g_V[(base + k0 + r) * DDIM + cc]);
    }
}

__global__ __launch_bounds__(256) void attn_tc_kernel() {
    extern __shared__ unsigned su[];
    unsigned* Qst = su;                        // [r][k] 128x132
    unsigned* Kst = Qst + 128 * QST;           // 2 x [k(feature)][c] 128x68
    unsigned* Vst = Kst + 2 * KSZ;             // 2 x [c][d] 64x68
    float*    Sst = (float*)(Vst + 2 * VSZ);   // [r][c] 128x68
    float*    row_m = Sst + 128 * SST;
    float*    row_l = row_m + 128;
    float*    alpha = row_l + 128;

    int q0 = blockIdx.x * 128;
    int bh = blockIdx.y;
    int t = threadIdx.x, lane = t & 31, wid = t >> 5;
    int m0w = wid * 16;
    const int base = bh * SSQ;
    const float scale = 0.03125f;  // 1/sqrt(1024)

    // prologue: Q' = [Q | Im] (already tf32-rounded) + first K/V tile
#pragma unroll
    for (int p = 0; p < 16; p++) {
        int c = t + p * 256;              // 4096 chunks
        int r = c >> 5, kc = (c & 31) * 4;
        const float* src = (kc < 64) ? &g_Q[(base + q0 + r) * DDIM + kc]
                                     : &g_Im[(base + q0 + r) * DDIM + kc - 64];
        cpa16(&Qst[r * QST + kc], src);
    }
    attn_load_kv(Kst, Vst, 0, bh, base, 0, t);
    CP_COMMIT();

    if (t < 128) { row_m[t] = -1e30f; row_l[t] = 0.f; }

    float OC[8][4];
#pragma unroll
    for (int nt = 0; nt < 8; nt++)
#pragma unroll
        for (int i = 0; i < 4; i++) OC[nt][i] = 0.f;

    for (int kt = 0; kt < 16; kt++) {
        int buf = kt & 1;
        if (kt + 1 < 16) {
            attn_load_kv(Kst, Vst, buf ^ 1, bh, base, (kt + 1) * 64, t);
            CP_COMMIT();
            CP_WAIT(1);
        } else {
            CP_WAIT(0);
        }
        __syncthreads();

        const unsigned* Kb = Kst + buf * KSZ;
        const unsigned* Vb = Vst + buf * VSZ;

        // S = Q' K'^T  (M=128/8 warps, N=64, K=128)
        float SC[8][4];
#pragma unroll
        for (int nt = 0; nt < 8; nt++)
#pragma unroll
            for (int i = 0; i < 4; i++) SC[nt][i] = 0.f;

#pragma unroll
        for (int ks = 0; ks < 16; ks++) {
            unsigned af[4];
            int r = m0w + (lane >> 2);
            int ck = ks * 8 + (lane & 3);
            af[0] = Qst[r * QST + ck];
            af[1] = Qst[(r + 8) * QST + ck];
            af[2] = Qst[r * QST + ck + 4];
            af[3] = Qst[(r + 8) * QST + ck + 4];
#pragma unroll
            for (int nt = 0; nt < 8; nt++) {
                unsigned bf[2];
                int kk = ks * 8 + (lane & 3);
                int cn = nt * 8 + (lane >> 2);
                bf[0] = Kb[kk * KST + cn];
                bf[1] = Kb[(kk + 4) * KST + cn];
                mma8(SC[nt], af, bf);
            }
        }
#pragma unroll
        for (int nt = 0; nt < 8; nt++) {
            int cc = nt * 8 + (lane & 3) * 2;
            int r = m0w + (lane >> 2);
            *(float2*)&Sst[r * SST + cc] = make_float2(SC[nt][0] * scale, SC[nt][1] * scale);
            *(float2*)&Sst[(r + 8) * SST + cc] = make_float2(SC[nt][2] * scale, SC[nt][3] * scale);
        }
        __syncthreads();

        // online softmax: 2 threads per row
        {
            int r = t >> 1, c0 = (t & 1) * 32;
            float mx = -1e30f;
#pragma unroll
            for (int i = 0; i < 32; i++) mx = fmaxf(mx, Sst[r * SST + c0 + i]);
            mx = fmaxf(mx, __shfl_xor_sync(0xffffffffu, mx, 1));
            float om = row_m[r];
            float nm = fmaxf(om, mx);
            float al = __expf(om - nm);
            float sum = 0.f;
#pragma unroll
            for (int i = 0; i < 32; i++) {
                float e = __expf(Sst[r * SST + c0 + i] - nm);
                sum += e;
                Sst[r * SST + c0 + i] = __uint_as_float(f2tf(e));
            }
            sum += __shfl_xor_sync(0xffffffffu, sum, 1);
            if ((t & 1) == 0) {
                row_l[r] = row_l[r] * al + sum;
                row_m[r] = nm;
                alpha[r] = al;
            }
        }
        __syncthreads();

        // rescale O accumulators
        {
            float al0 = alpha[m0w + (lane >> 2)];
            float al1 = alpha[m0w + (lane >> 2) + 8];
#pragma unroll
            for (int nt = 0; nt < 8; nt++) {
                OC[nt][0] *= al0; OC[nt][1] *= al0;
                OC[nt][2] *= al1; OC[nt][3] *= al1;
            }
        }

        // O += P @ V  (K=64)
        const unsigned* Su = (const unsigned*)Sst;
#pragma unroll
        for (int ks = 0; ks < 8; ks++) {
            unsigned af[4];
            int r = m0w + (lane >> 2);
            int ck = ks * 8 + (lane & 3);
            af[0] = Su[r * SST + ck];
            af[1] = Su[(r + 8) * SST + ck];
            af[2] = Su[r * SST + ck + 4];
            af[3] = Su[(r + 8) * SST + ck + 4];
#pragma unroll
            for (int nt = 0; nt < 8; nt++) {
                unsigned bf[2];
                int kk = ks * 8 + (lane & 3);
                int dn = nt * 8 + (lane >> 2);
                bf[0] = Vb[kk * VST + dn];
                bf[1] = Vb[(kk + 4) * VST + dn];
                mma8(OC[nt], af, bf);
            }
        }
        __syncthreads();
    }

    // finalize: /row_l, write merged [b, s, h*64+d], tf32-rounded for out GEMM
    int b = bh >> 4, h = bh & 15;
    {
        int r0 = m0w + (lane >> 2);
        float li0 = 1.0f / row_l[r0];
        float li1 = 1.0f / row_l[r0 + 8];
#pragma unroll
        for (int nt = 0; nt < 8; nt++) {
            int d = nt * 8 + (lane & 3) * 2;
            int s0 = q0 + r0;
            *(float2*)&g_AO[(b * SSQ + s0) * EE + h * DDIM + d] =
                make_float2(rtf(OC[nt][0] * li0), rtf(OC[nt][1] * li0));
            *(float2*)&g_AO[(b * SSQ + s0 + 8) * EE + h * DDIM + d] =
                make_float2(rtf(OC[nt][2] * li1), rtf(OC[nt][3] * li1));
        }
    }
}

// ---------------------------------------------------------------------------
// Kernel 3: output GEMM: out = g_AO @ Wo + bo (cp.async double buffer)
// ---------------------------------------------------------------------------
__global__ __launch_bounds__(256) void out_tc_kernel(
    const float* __restrict__ bias, float* __restrict__ out)
{
    extern __shared__ unsigned gsm[];
    unsigned* As = gsm;
    unsigned* Bs = gsm + 2 * ASZ;

    int m0 = blockIdx.y * 128, n0 = blockIdx.x * 128;
    int t = threadIdx.x, lane = t & 31, wid = t >> 5;
    int wm = (wid & 1) * 64, wn = (wid >> 1) * 32;

    float C[4][4][4];
#pragma unroll
    for (int mt = 0; mt < 4; mt++)
#pragma unroll
        for (int nt = 0; nt < 4; nt++)
#pragma unroll
            for (int i = 0; i < 4; i++) C[mt][nt][i] = 0.f;

    const float* W = g_Wc[3];
    const int NSTEP = EE / 32;
    gemm_load_tiles(As, Bs, 0, g_AO, W, m0, n0, 0, t);
    CP_COMMIT();

    for (int it = 0; it < NSTEP; it++) {
        int buf = it & 1;
        if (it + 1 < NSTEP) {
            gemm_load_tiles(As, Bs, buf ^ 1, g_AO, W, m0, n0, (it + 1) * 32, t);
            CP_COMMIT();
            CP_WAIT(1);
        } else {
            CP_WAIT(0);
        }
        __syncthreads();
        gemm_compute(As, Bs, buf, C, wm, wn, lane);
        __syncthreads();
    }

#pragma unroll
    for (int mt = 0; mt < 4; mt++) {
#pragma unroll
        for (int rr = 0; rr < 2; rr++) {
            int m = m0 + wm + mt * 16 + (lane >> 2) + rr * 8;
#pragma unroll
            for (int nt = 0; nt < 4; nt++) {
                int c = n0 + wn + nt * 8 + (lane & 3) * 2;
                float v0 = C[mt][nt][rr * 2 + 0] + bias[c];
                float v1 = C[mt][nt][rr * 2 + 1] + bias[c + 1];
                *(float2*)&out[m * EE + c] = make_float2(v0, v1);
            }
        }
    }
}

// ---------------------------------------------------------------------------
extern "C" void kernel_launch(void* const* d_in, const int* in_sizes, int n_in,
                              void* d_out, int out_size) {
    const float* Re  = (const float*)d_in[0];
    const float* Im  = (const float*)d_in[1];
    const float* pos = (const float*)d_in[2];
    const float* Wq  = (const float*)d_in[3];
    const float* bq  = (const float*)d_in[4];
    const float* Wk  = (const float*)d_in[5];
    const float* bk  = (const float*)d_in[6];
    const float* Wv  = (const float*)d_in[7];
    const float* bv  = (const float*)d_in[8];
    const float* Wo  = (const float*)d_in[9];
    const float* bo  = (const float*)d_in[10];
    float* out = (float*)d_out;

    cudaFuncSetAttribute(attn_tc_kernel, cudaFuncAttributeMaxDynamicSharedMemorySize,
                         ATTN_SMEM_BYTES);
    cudaFuncSetAttribute(qkv_tc_kernel, cudaFuncAttributeMaxDynamicSharedMemorySize,
                         GEMM_SMEM_BYTES);
    cudaFuncSetAttribute(out_tc_kernel, cudaFuncAttributeMaxDynamicSharedMemorySize,
                         GEMM_SMEM_BYTES);

    conv_tf32_kernel<<<(MM * EE) / 256, 256>>>(Re, 0);
    conv_tf32_kernel<<<(EE * EE) / 256, 256>>>(Wq, 1);
    conv_tf32_kernel<<<(EE * EE) / 256, 256>>>(Wk, 2);
    conv_tf32_kernel<<<(EE * EE) / 256, 256>>>(Wv, 3);
    conv_tf32_kernel<<<(EE * EE) / 256, 256>>>(Wo, 4);
    pack_im_kernel<<<(NBH * SSQ * DDIM) / 256, 256>>>(Im);
    qkv_tc_kernel<<<dim3(EE / 128, MM / 128, 3), 256, GEMM_SMEM_BYTES>>>(bq, bk, bv, pos);
    attn_tc_kernel<<<dim3(SSQ / 128, NBH), 256, ATTN_SMEM_BYTES>>>();
    out_tc_kernel<<<dim3(EE / 128, MM / 128), 256, GEMM_SMEM_BYTES>>>(bo, out);
}